// round 2
// baseline (speedup 1.0000x reference)
#include <cuda_runtime.h>

// TensorProduct: out[b,0,n,f] = sum_{l,m} x1[b,0,l,f]*x2[b,0,m,f]*cg[l,m,n] * pe[0]
//                out[b,1,n,f] = same * pe[1]
//
// Shapes: x1 (2048,1,9,512) f32, x2 (2048,1,9,512) f32, cg (9,9,25) f32,
//         parity_even (2,1) f32, out (2048,2,25,512) f32.
//
// R2: l3-outermost restructure. Live accumulator is only the current l3 block
// (<= 9 float2), stores issue per-block (overlap with next block's FMAs), and
// register pressure drops ~111 -> ~64 so 4 CTAs/SM fit (occupancy 2x).
// CG values still read at runtime from shared memory; the compile-time guards
// are a structural superset of the true nonzeros (over-inclusion multiplies by 0).

#define F2 256           // 512 floats per row = 256 float2

__global__ void __launch_bounds__(256, 4)
tp_kernel(const float* __restrict__ x1,
          const float* __restrict__ x2,
          const float* __restrict__ cg,
          const float* __restrict__ pe,
          float* __restrict__ out)
{
    __shared__ float scg[9 * 9 * 25];   // 8100 B
    for (int t = threadIdx.x; t < 9 * 9 * 25; t += blockDim.x)
        scg[t] = cg[t];
    __syncthreads();

    const int g  = blockIdx.x * blockDim.x + threadIdx.x;  // 0 .. 524287
    const int f2 = g & (F2 - 1);
    const int b  = g >> 8;

    const float2* __restrict__ X1 =
        reinterpret_cast<const float2*>(x1) + (size_t)b * 9 * F2 + f2;
    const float2* __restrict__ X2 =
        reinterpret_cast<const float2*>(x2) + (size_t)b * 9 * F2 + f2;

    float2 a[9], c[9];
    #pragma unroll
    for (int l = 0; l < 9; l++) { a[l] = X1[l * F2]; }
    #pragma unroll
    for (int l = 0; l < 9; l++) { c[l] = X2[l * F2]; }

    const float pe0 = pe[0];
    const float pe1 = pe[1];

    float2* __restrict__ O =
        reinterpret_cast<float2*>(out) + (size_t)b * 50 * F2 + f2;

    // l3-outermost: accumulator for one output block at a time.
    #pragma unroll
    for (int l3 = 0; l3 <= 4; l3++) {
        float2 acc[9];   // only 2*l3+1 entries used
        #pragma unroll
        for (int q = 0; q < 9; q++) acc[q] = make_float2(0.f, 0.f);

        #pragma unroll
        for (int l1 = 0; l1 <= 2; l1++) {
            #pragma unroll
            for (int l2 = 0; l2 <= 2; l2++) {
                // triangle rule at compile time
                const int lo = (l1 > l2) ? (l1 - l2) : (l2 - l1);
                if (l3 < lo || l3 > l1 + l2) continue;
                #pragma unroll
                for (int m1 = -2; m1 <= 2; m1++) {
                    if (m1 < -l1 || m1 > l1) continue;
                    const int i  = l1 * (l1 + 1) + m1;
                    const int a1 = m1 < 0 ? -m1 : m1;
                    #pragma unroll
                    for (int m2 = -2; m2 <= 2; m2++) {
                        if (m2 < -l2 || m2 > l2) continue;
                        const int j  = l2 * (l2 + 1) + m2;
                        const int a2 = m2 < 0 ? -m2 : m2;

                        float2 p;
                        p.x = a[i].x * c[j].x;
                        p.y = a[i].y * c[j].y;

                        #pragma unroll
                        for (int m3 = -4; m3 <= 4; m3++) {
                            if (m3 < -l3 || m3 > l3) continue;
                            const int a3 = m3 < 0 ? -m3 : m3;
                            // |m| selection rule
                            const bool sel = (a3 == a1 + a2) ||
                                             (a3 == a1 - a2) ||
                                             (a3 == a2 - a1);
                            // parity rule (exact real-basis CG support)
                            const int par = (l1 + l2 + l3 + a1 + a2 + a3 +
                                             (m1 < 0 ? 1 : 0) +
                                             (m2 < 0 ? 1 : 0) +
                                             (m3 < 0 ? 1 : 0)) & 1;
                            if (!sel || par) continue;

                            const int k = l3 * (l3 + 1) + m3;       // global n
                            const int q = m3 + l3;                  // block-local
                            const float w = scg[(i * 9 + j) * 25 + k];
                            acc[q].x = fmaf(w, p.x, acc[q].x);
                            acc[q].y = fmaf(w, p.y, acc[q].y);
                        }
                    }
                }
            }
        }

        // store this l3 block immediately (both parity planes)
        const int nbase = l3 * l3;
        #pragma unroll
        for (int q = 0; q < 9; q++) {
            if (q > 2 * l3) continue;
            const int n = nbase + q;
            float2 v0 = make_float2(pe0 * acc[q].x, pe0 * acc[q].y);
            float2 v1 = make_float2(pe1 * acc[q].x, pe1 * acc[q].y);
            O[n * F2]        = v0;
            O[(25 + n) * F2] = v1;
        }
    }
}

extern "C" void kernel_launch(void* const* d_in, const int* in_sizes, int n_in,
                              void* d_out, int out_size)
{
    const float* x1 = (const float*)d_in[0];
    const float* x2 = (const float*)d_in[1];
    const float* cg = (const float*)d_in[2];
    const float* pe = (const float*)d_in[3];
    float* out = (float*)d_out;

    tp_kernel<<<2048, 256>>>(x1, x2, cg, pe, out);
}

// round 3
// speedup vs baseline: 1.3371x; 1.3371x over previous
#include <cuda_runtime.h>

// TensorProduct: out[b,0,n,f] = sum_{l,m} x1[b,0,l,f]*x2[b,0,m,f]*cg[l,m,n] * pe[0]
//                out[b,1,n,f] = same * pe[1]
//
// Shapes: x1 (2048,1,9,512) f32, x2 (2048,1,9,512) f32, cg (9,9,25) f32,
//         parity_even (2,1) f32, out (2048,2,25,512) f32.
//
// R3: two-pass l3 blocking. Pass A: l3 in {0,1,2} (9 float2 acc), pass B:
// l3 in {3,4} (16 float2 acc). Peak regs ~83 fits 3 CTAs/SM under
// __launch_bounds__(256,3) WITHOUT spilling (R2's 64-reg cap spilled and
// doubled DRAM traffic). Products recomputed per pass (fma pipe has headroom).

#define F2 256           // 512 floats per row = 256 float2

template<int L3LO, int L3HI, int NACC>
__device__ __forceinline__ void contract_pass(
    const float2 (&a)[9], const float2 (&c)[9],
    const float* __restrict__ scg,
    float pe0, float pe1,
    float2* __restrict__ O)
{
    float2 acc[NACC];
    #pragma unroll
    for (int q = 0; q < NACC; q++) acc[q] = make_float2(0.f, 0.f);

    #pragma unroll
    for (int l1 = 0; l1 <= 2; l1++) {
        #pragma unroll
        for (int m1 = -2; m1 <= 2; m1++) {
            if (m1 < -l1 || m1 > l1) continue;
            const int i  = l1 * (l1 + 1) + m1;
            const int a1 = m1 < 0 ? -m1 : m1;
            #pragma unroll
            for (int l2 = 0; l2 <= 2; l2++) {
                // skip (l1,l2) pairs with no l3 in [L3LO,L3HI]
                const int lo = (l1 > l2) ? (l1 - l2) : (l2 - l1);
                const int hi = l1 + l2;
                if (hi < L3LO || lo > L3HI) continue;
                #pragma unroll
                for (int m2 = -2; m2 <= 2; m2++) {
                    if (m2 < -l2 || m2 > l2) continue;
                    const int j  = l2 * (l2 + 1) + m2;
                    const int a2 = m2 < 0 ? -m2 : m2;

                    float2 p;
                    p.x = a[i].x * c[j].x;
                    p.y = a[i].y * c[j].y;

                    #pragma unroll
                    for (int l3 = L3LO; l3 <= L3HI; l3++) {
                        if (l3 < lo || l3 > hi) continue;
                        #pragma unroll
                        for (int m3 = -4; m3 <= 4; m3++) {
                            if (m3 < -l3 || m3 > l3) continue;
                            const int a3 = m3 < 0 ? -m3 : m3;
                            const bool sel = (a3 == a1 + a2) ||
                                             (a3 == a1 - a2) ||
                                             (a3 == a2 - a1);
                            const int par = (l1 + l2 + l3 + a1 + a2 + a3 +
                                             (m1 < 0 ? 1 : 0) +
                                             (m2 < 0 ? 1 : 0) +
                                             (m3 < 0 ? 1 : 0)) & 1;
                            if (!sel || par) continue;

                            const int k = l3 * (l3 + 1) + m3;         // global n
                            const int q = k - L3LO * L3LO;            // pass-local
                            const float w = scg[(i * 9 + j) * 25 + k];
                            acc[q].x = fmaf(w, p.x, acc[q].x);
                            acc[q].y = fmaf(w, p.y, acc[q].y);
                        }
                    }
                }
            }
        }
    }

    // store this pass's blocks (both parity planes)
    #pragma unroll
    for (int q = 0; q < NACC; q++) {
        const int n = L3LO * L3LO + q;
        float2 v0 = make_float2(pe0 * acc[q].x, pe0 * acc[q].y);
        float2 v1 = make_float2(pe1 * acc[q].x, pe1 * acc[q].y);
        O[n * F2]        = v0;
        O[(25 + n) * F2] = v1;
    }
}

__global__ void __launch_bounds__(256, 3)
tp_kernel(const float* __restrict__ x1,
          const float* __restrict__ x2,
          const float* __restrict__ cg,
          const float* __restrict__ pe,
          float* __restrict__ out)
{
    __shared__ float scg[9 * 9 * 25];   // 8100 B
    for (int t = threadIdx.x; t < 9 * 9 * 25; t += blockDim.x)
        scg[t] = cg[t];
    __syncthreads();

    const int g  = blockIdx.x * blockDim.x + threadIdx.x;  // 0 .. 524287
    const int f2 = g & (F2 - 1);
    const int b  = g >> 8;

    const float2* __restrict__ X1 =
        reinterpret_cast<const float2*>(x1) + (size_t)b * 9 * F2 + f2;
    const float2* __restrict__ X2 =
        reinterpret_cast<const float2*>(x2) + (size_t)b * 9 * F2 + f2;

    float2 a[9], c[9];
    #pragma unroll
    for (int l = 0; l < 9; l++) { a[l] = X1[l * F2]; }
    #pragma unroll
    for (int l = 0; l < 9; l++) { c[l] = X2[l * F2]; }

    const float pe0 = pe[0];
    const float pe1 = pe[1];

    float2* __restrict__ O =
        reinterpret_cast<float2*>(out) + (size_t)b * 50 * F2 + f2;

    // Pass A: l3 = 0,1,2  -> n = 0..8   (9 accumulators)
    contract_pass<0, 2, 9>(a, c, scg, pe0, pe1, O);
    // Pass B: l3 = 3,4    -> n = 9..24  (16 accumulators)
    contract_pass<3, 4, 16>(a, c, scg, pe0, pe1, O);
}

extern "C" void kernel_launch(void* const* d_in, const int* in_sizes, int n_in,
                              void* d_out, int out_size)
{
    const float* x1 = (const float*)d_in[0];
    const float* x2 = (const float*)d_in[1];
    const float* cg = (const float*)d_in[2];
    const float* pe = (const float*)d_in[3];
    float* out = (float*)d_out;

    tp_kernel<<<2048, 256>>>(x1, x2, cg, pe, out);
}

// round 4
// speedup vs baseline: 1.6211x; 1.2124x over previous
#include <cuda_runtime.h>

// TensorProduct: out[b,0,n,f] = sum_{l,m} x1[b,0,l,f]*x2[b,0,m,f]*cg[l,m,n] * pe[0]
//                out[b,1,n,f] = same * pe[1]
//
// Shapes: x1 (2048,1,9,512) f32, x2 (2048,1,9,512) f32, cg (9,9,25) f32,
//         parity_even (2,1) f32, out (2048,2,25,512) f32.
//
// R4: ONE float per thread (scalar). Single-pass full contraction, acc[25]
// floats. Natural register need ~58 -> fits 3 CTAs/SM (85-reg cap) with a
// wide no-spill margin. R2/R3 proved spills are fatal; R1 proved occupancy
// 22% leaves DRAM at 55%. This gets occupancy ~37% at ZERO spill.
// CG values read at runtime from shared; compile-time guards are a structural
// superset of the true nonzeros (over-inclusion multiplies by 0).

__global__ void __launch_bounds__(256, 3)
tp_kernel(const float* __restrict__ x1,
          const float* __restrict__ x2,
          const float* __restrict__ cg,
          const float* __restrict__ pe,
          float* __restrict__ out)
{
    __shared__ float scg[9 * 9 * 25];   // 8100 B
    for (int t = threadIdx.x; t < 9 * 9 * 25; t += blockDim.x)
        scg[t] = cg[t];
    __syncthreads();

    const int g = blockIdx.x * blockDim.x + threadIdx.x;   // 0 .. 1048575
    const int f = g & 511;
    const int b = g >> 9;

    const float* __restrict__ X1 = x1 + (size_t)b * 9 * 512 + f;
    const float* __restrict__ X2 = x2 + (size_t)b * 9 * 512 + f;

    float a[9], c[9];
    #pragma unroll
    for (int l = 0; l < 9; l++) a[l] = X1[l * 512];
    #pragma unroll
    for (int l = 0; l < 9; l++) c[l] = X2[l * 512];

    float acc[25];
    #pragma unroll
    for (int n = 0; n < 25; n++) acc[n] = 0.f;

    // Fully unrolled sparse contraction; guards prune structurally-zero CG.
    #pragma unroll
    for (int l1 = 0; l1 <= 2; l1++) {
        #pragma unroll
        for (int m1 = -2; m1 <= 2; m1++) {
            if (m1 < -l1 || m1 > l1) continue;
            const int i  = l1 * (l1 + 1) + m1;
            const int a1 = m1 < 0 ? -m1 : m1;
            #pragma unroll
            for (int l2 = 0; l2 <= 2; l2++) {
                #pragma unroll
                for (int m2 = -2; m2 <= 2; m2++) {
                    if (m2 < -l2 || m2 > l2) continue;
                    const int j  = l2 * (l2 + 1) + m2;
                    const int a2 = m2 < 0 ? -m2 : m2;

                    const float p = a[i] * c[j];

                    const int lo = (l1 > l2) ? (l1 - l2) : (l2 - l1);
                    const int hi = (l1 + l2) < 4 ? (l1 + l2) : 4;
                    #pragma unroll
                    for (int l3 = 0; l3 <= 4; l3++) {
                        if (l3 < lo || l3 > hi) continue;
                        #pragma unroll
                        for (int m3 = -4; m3 <= 4; m3++) {
                            if (m3 < -l3 || m3 > l3) continue;
                            const int a3 = m3 < 0 ? -m3 : m3;
                            const bool sel = (a3 == a1 + a2) ||
                                             (a3 == a1 - a2) ||
                                             (a3 == a2 - a1);
                            const int par = (l1 + l2 + l3 + a1 + a2 + a3 +
                                             (m1 < 0 ? 1 : 0) +
                                             (m2 < 0 ? 1 : 0) +
                                             (m3 < 0 ? 1 : 0)) & 1;
                            if (!sel || par) continue;

                            const int k = l3 * (l3 + 1) + m3;   // 0..24
                            const float w = scg[(i * 9 + j) * 25 + k];
                            acc[k] = fmaf(w, p, acc[k]);
                        }
                    }
                }
            }
        }
    }

    const float pe0 = pe[0];
    const float pe1 = pe[1];

    float* __restrict__ O = out + (size_t)b * 50 * 512 + f;

    #pragma unroll
    for (int n = 0; n < 25; n++) {
        O[n * 512]        = pe0 * acc[n];   // even parity plane
        O[(25 + n) * 512] = pe1 * acc[n];   // odd parity plane
    }
}

extern "C" void kernel_launch(void* const* d_in, const int* in_sizes, int n_in,
                              void* d_out, int out_size)
{
    const float* x1 = (const float*)d_in[0];
    const float* x2 = (const float*)d_in[1];
    const float* cg = (const float*)d_in[2];
    const float* pe = (const float*)d_in[3];
    float* out = (float*)d_out;

    // 2048 batches * 512 lanes = 1048576 threads
    tp_kernel<<<4096, 256>>>(x1, x2, cg, pe, out);
}

// round 5
// speedup vs baseline: 1.8740x; 1.1560x over previous
#include <cuda_runtime.h>

// TensorProduct: out[b,0,n,f] = sum_{l,m} x1[b,0,l,f]*x2[b,0,m,f]*cg[l,m,n] * pe[0]
//                out[b,1,n,f] = same * pe[1]
//
// Shapes: x1 (2048,1,9,512) f32, x2 (2048,1,9,512) f32, cg (9,9,25) f32,
//         parity_even (2,1) f32, out (2048,2,25,512) f32.
//
// R5: float2 per thread + l3-split across PAIRED CTAs in ONE launch.
// Even bid -> pass A: l3 in {0,1,2} (9 float2 acc); odd bid -> pass B:
// l3 in {3,4} (16 float2 acc). Both use tile = bid>>1, so the pair is
// wave-adjacent and the second x1/x2 read hits L2. No register caps
// (R2/R3 proved spills are fatal). LDS-per-output-byte drops ~4x vs R4.
// The pass split is a compile-time-constant branch on (blockIdx.x & 1):
// both sides fully unrolled; register allocation is the max of the two
// (~84), still well under spill territory with no cap.

#define F2 256           // 512 floats per row = 256 float2

template<int L3LO, int L3HI, int NACC>
__device__ __forceinline__ void run_pass(
    const float2 (&a)[9], const float2 (&c)[9],
    const float* __restrict__ scg,
    float pe0, float pe1,
    float2* __restrict__ O)
{
    float2 acc[NACC];
    #pragma unroll
    for (int q = 0; q < NACC; q++) acc[q] = make_float2(0.f, 0.f);

    #pragma unroll
    for (int l1 = 0; l1 <= 2; l1++) {
        #pragma unroll
        for (int m1 = -2; m1 <= 2; m1++) {
            if (m1 < -l1 || m1 > l1) continue;
            const int i  = l1 * (l1 + 1) + m1;
            const int a1 = m1 < 0 ? -m1 : m1;
            #pragma unroll
            for (int l2 = 0; l2 <= 2; l2++) {
                const int lo = (l1 > l2) ? (l1 - l2) : (l2 - l1);
                const int hi = l1 + l2;
                if (hi < L3LO || lo > L3HI) continue;   // pass has no l3 here
                #pragma unroll
                for (int m2 = -2; m2 <= 2; m2++) {
                    if (m2 < -l2 || m2 > l2) continue;
                    const int j  = l2 * (l2 + 1) + m2;
                    const int a2 = m2 < 0 ? -m2 : m2;

                    float2 p;
                    p.x = a[i].x * c[j].x;
                    p.y = a[i].y * c[j].y;

                    #pragma unroll
                    for (int l3 = L3LO; l3 <= L3HI; l3++) {
                        if (l3 < lo || l3 > hi) continue;
                        #pragma unroll
                        for (int m3 = -4; m3 <= 4; m3++) {
                            if (m3 < -l3 || m3 > l3) continue;
                            const int a3 = m3 < 0 ? -m3 : m3;
                            const bool sel = (a3 == a1 + a2) ||
                                             (a3 == a1 - a2) ||
                                             (a3 == a2 - a1);
                            const int par = (l1 + l2 + l3 + a1 + a2 + a3 +
                                             (m1 < 0 ? 1 : 0) +
                                             (m2 < 0 ? 1 : 0) +
                                             (m3 < 0 ? 1 : 0)) & 1;
                            if (!sel || par) continue;

                            const int k = l3 * (l3 + 1) + m3;   // global n
                            const int q = k - L3LO * L3LO;      // pass-local
                            const float w = scg[(i * 9 + j) * 25 + k];
                            acc[q].x = fmaf(w, p.x, acc[q].x);
                            acc[q].y = fmaf(w, p.y, acc[q].y);
                        }
                    }
                }
            }
        }
    }

    #pragma unroll
    for (int q = 0; q < NACC; q++) {
        const int n = L3LO * L3LO + q;
        float2 v0 = make_float2(pe0 * acc[q].x, pe0 * acc[q].y);
        float2 v1 = make_float2(pe1 * acc[q].x, pe1 * acc[q].y);
        O[n * F2]        = v0;
        O[(25 + n) * F2] = v1;
    }
}

__global__ void __launch_bounds__(256)
tp_kernel(const float* __restrict__ x1,
          const float* __restrict__ x2,
          const float* __restrict__ cg,
          const float* __restrict__ pe,
          float* __restrict__ out)
{
    __shared__ float scg[9 * 9 * 25];   // 8100 B
    for (int t = threadIdx.x; t < 9 * 9 * 25; t += blockDim.x)
        scg[t] = cg[t];
    __syncthreads();

    const int pass = blockIdx.x & 1;
    const int tile = blockIdx.x >> 1;                 // 0..2047 (=batch)
    const int g    = tile * blockDim.x + threadIdx.x; // 0..524287
    const int f2   = g & (F2 - 1);
    const int b    = g >> 8;

    const float2* __restrict__ X1 =
        reinterpret_cast<const float2*>(x1) + (size_t)b * 9 * F2 + f2;
    const float2* __restrict__ X2 =
        reinterpret_cast<const float2*>(x2) + (size_t)b * 9 * F2 + f2;

    float2 a[9], c[9];
    #pragma unroll
    for (int l = 0; l < 9; l++) a[l] = X1[l * F2];
    #pragma unroll
    for (int l = 0; l < 9; l++) c[l] = X2[l * F2];

    const float pe0 = pe[0];
    const float pe1 = pe[1];

    float2* __restrict__ O =
        reinterpret_cast<float2*>(out) + (size_t)b * 50 * F2 + f2;

    if (pass == 0) {
        run_pass<0, 2, 9>(a, c, scg, pe0, pe1, O);    // n = 0..8
    } else {
        run_pass<3, 4, 16>(a, c, scg, pe0, pe1, O);   // n = 9..24
    }
}

extern "C" void kernel_launch(void* const* d_in, const int* in_sizes, int n_in,
                              void* d_out, int out_size)
{
    const float* x1 = (const float*)d_in[0];
    const float* x2 = (const float*)d_in[1];
    const float* cg = (const float*)d_in[2];
    const float* pe = (const float*)d_in[3];
    float* out = (float*)d_out;

    // 4096 CTAs: even/odd pairs share a (b, f2) tile -> L2 reuse of x1/x2.
    tp_kernel<<<4096, 256>>>(x1, x2, cg, pe, out);
}

// round 6
// speedup vs baseline: 1.8813x; 1.0039x over previous
#include <cuda_runtime.h>

// TensorProduct: out[b,0,n,f] = sum_{l,m} x1[b,0,l,f]*x2[b,0,m,f]*cg[l,m,n] * pe[0]
//                out[b,1,n,f] = same * pe[1]
//
// Shapes: x1 (2048,1,9,512) f32, x2 (2048,1,9,512) f32, cg (9,9,25) f32,
//         parity_even (2,1) f32, out (2048,2,25,512) f32.
//
// R6: R5 (float2/thread, l3-split across even/odd paired CTAs) + CG swap
// symmetry folding: C[i,j,k] = (-1)^(l1+l2+l3) C[j,i,k], so unordered pairs
// (i,j) share one weight load and one FMA via pp/pm = a_i*c_j +- a_j*c_i.
// Diagonal blocks with odd l3 are antisymmetric -> structurally zero, skipped.
// Streaming stores (__stcs) keep L2 for the paired x1/x2 reuse.

#define F2 256           // 512 floats per row = 256 float2

template<int L3LO, int L3HI, int NACC>
__device__ __forceinline__ void run_pass(
    const float2 (&a)[9], const float2 (&c)[9],
    const float* __restrict__ scg,
    float pe0, float pe1,
    float2* __restrict__ O)
{
    float2 acc[NACC];
    #pragma unroll
    for (int q = 0; q < NACC; q++) acc[q] = make_float2(0.f, 0.f);

    #pragma unroll
    for (int i = 0; i < 9; i++) {
        const int l1 = (i >= 4) ? 2 : (i >= 1) ? 1 : 0;
        const int m1 = i - l1 * (l1 + 1);
        const int a1 = m1 < 0 ? -m1 : m1;
        #pragma unroll
        for (int j = i; j < 9; j++) {
            const int l2 = (j >= 4) ? 2 : (j >= 1) ? 1 : 0;
            const int m2 = j - l2 * (l2 + 1);
            const int a2 = m2 < 0 ? -m2 : m2;

            const int lo = (l1 > l2) ? (l1 - l2) : (l2 - l1);
            const int hi = l1 + l2;
            if (hi < L3LO || lo > L3HI) continue;   // pass has no l3 here

            // pp = a_i*c_j + a_j*c_i ; pm = a_i*c_j - a_j*c_i
            float2 pp, pm;
            if (i == j) {
                pp.x = a[i].x * c[i].x;
                pp.y = a[i].y * c[i].y;
                pm = pp;                 // never used (odd-l3 diag skipped)
            } else {
                float ux = a[i].x * c[j].x, uy = a[i].y * c[j].y;
                float vx = a[j].x * c[i].x, vy = a[j].y * c[i].y;
                pp.x = ux + vx;  pp.y = uy + vy;
                pm.x = ux - vx;  pm.y = uy - vy;
            }

            #pragma unroll
            for (int l3 = 0; l3 <= 4; l3++) {
                if (l3 < L3LO || l3 > L3HI || l3 < lo || l3 > hi) continue;
                const bool neg = ((l1 + l2 + l3) & 1) != 0;
                if (i == j && neg) continue;   // antisymmetric block: diag = 0

                #pragma unroll
                for (int m3 = -4; m3 <= 4; m3++) {
                    if (m3 < -l3 || m3 > l3) continue;
                    const int a3 = m3 < 0 ? -m3 : m3;
                    // |m| selection rule
                    const bool sel = (a3 == a1 + a2) ||
                                     (a3 == a1 - a2) ||
                                     (a3 == a2 - a1);
                    // parity rule (exact real-basis CG support)
                    const int par = (l1 + l2 + l3 + a1 + a2 + a3 +
                                     (m1 < 0 ? 1 : 0) +
                                     (m2 < 0 ? 1 : 0) +
                                     (m3 < 0 ? 1 : 0)) & 1;
                    if (!sel || par) continue;

                    const int k = l3 * (l3 + 1) + m3;   // global n
                    const int q = k - L3LO * L3LO;      // pass-local
                    const float w = scg[(i * 9 + j) * 25 + k];
                    const float2 t = neg ? pm : pp;     // compile-time select
                    acc[q].x = fmaf(w, t.x, acc[q].x);
                    acc[q].y = fmaf(w, t.y, acc[q].y);
                }
            }
        }
    }

    #pragma unroll
    for (int q = 0; q < NACC; q++) {
        const int n = L3LO * L3LO + q;
        float2 v0 = make_float2(pe0 * acc[q].x, pe0 * acc[q].y);
        float2 v1 = make_float2(pe1 * acc[q].x, pe1 * acc[q].y);
        __stcs(&O[n * F2], v0);          // even parity plane (streaming)
        __stcs(&O[(25 + n) * F2], v1);   // odd parity plane
    }
}

__global__ void __launch_bounds__(256)
tp_kernel(const float* __restrict__ x1,
          const float* __restrict__ x2,
          const float* __restrict__ cg,
          const float* __restrict__ pe,
          float* __restrict__ out)
{
    __shared__ float scg[9 * 9 * 25];   // 8100 B
    for (int t = threadIdx.x; t < 9 * 9 * 25; t += blockDim.x)
        scg[t] = cg[t];
    __syncthreads();

    const int pass = blockIdx.x & 1;
    const int tile = blockIdx.x >> 1;                 // 0..2047
    const int g    = tile * blockDim.x + threadIdx.x; // 0..524287
    const int f2   = g & (F2 - 1);
    const int b    = g >> 8;

    const float2* __restrict__ X1 =
        reinterpret_cast<const float2*>(x1) + (size_t)b * 9 * F2 + f2;
    const float2* __restrict__ X2 =
        reinterpret_cast<const float2*>(x2) + (size_t)b * 9 * F2 + f2;

    float2 a[9], c[9];
    #pragma unroll
    for (int l = 0; l < 9; l++) a[l] = X1[l * F2];
    #pragma unroll
    for (int l = 0; l < 9; l++) c[l] = X2[l * F2];

    const float pe0 = pe[0];
    const float pe1 = pe[1];

    float2* __restrict__ O =
        reinterpret_cast<float2*>(out) + (size_t)b * 50 * F2 + f2;

    if (pass == 0) {
        run_pass<0, 2, 9>(a, c, scg, pe0, pe1, O);    // n = 0..8
    } else {
        run_pass<3, 4, 16>(a, c, scg, pe0, pe1, O);   // n = 9..24
    }
}

extern "C" void kernel_launch(void* const* d_in, const int* in_sizes, int n_in,
                              void* d_out, int out_size)
{
    const float* x1 = (const float*)d_in[0];
    const float* x2 = (const float*)d_in[1];
    const float* cg = (const float*)d_in[2];
    const float* pe = (const float*)d_in[3];
    float* out = (float*)d_out;

    // 4096 CTAs: even/odd pairs share a (b, f2) tile -> L2 reuse of x1/x2.
    tp_kernel<<<4096, 256>>>(x1, x2, cg, pe, out);
}